// round 13
// baseline (speedup 1.0000x reference)
#include <cuda_runtime.h>
#include <cstdint>
#include <math.h>

// Problem constants: x is (64, 128, 10000) fp32.
#define BATCH 64
#define CH    128
#define T_LEN 10000
#define TT    32            // time-chunk per pipeline stage
#define PITCH 36            // floats; 144B rows: 16B-aligned, ≡4 mod 32 banks
#define NCHUNK 313          // ceil(10000/32); last chunk vlen=16
#define GX    56            // chunk stride; grid (56, 8) = 448 blocks
#define GBATCH 8            // batches per group
#define GROUPS (BATCH / GBATCH)
#define NBUF  3             // pipeline depth (2 chunks in flight)
#define NBLOCKS (GX * GBATCH)
#define T4    (T_LEN / 4)   // 2500
#define NTILE 5             // ceil(2500/512) norm tiles per (b,c)
#define TILE_FLOATS (CH * PITCH)

// Scratch (no allocations allowed). Statically zero-initialized.
__device__ float g_m[BATCH * T_LEN];        // mean over channels at each (b,t)
__device__ float g_sum [BATCH * CH];        // accumulator (zeroed by kernel 0 each call)
__device__ float g_sum2[BATCH * CH];
__device__ unsigned g_bar_cnt = 0;          // grid barrier state (replay-safe)
__device__ volatile unsigned g_bar_gen = 0; // monotonic generation

__device__ __forceinline__ void cp_async16(unsigned sdst, const void* gsrc) {
    asm volatile("cp.async.cg.shared.global [%0], [%1], 16;\n"
                 :: "r"(sdst), "l"(gsrc));
}
__device__ __forceinline__ void cp_commit() {
    asm volatile("cp.async.commit_group;\n");
}
template <int N>
__device__ __forceinline__ void cp_wait() {
    asm volatile("cp.async.wait_group %0;\n" :: "n"(N));
}

// Grid-wide barrier. All NBLOCKS blocks are resident (capacity 4/SM * 148 = 592 >= 448),
// so spinning is safe. Generation counter is monotonic -> safe across graph replays.
__device__ __forceinline__ void grid_barrier() {
    __syncthreads();
    if (threadIdx.x == 0) {
        __threadfence();                       // make this block's writes visible
        unsigned gen = g_bar_gen;
        if (atomicAdd(&g_bar_cnt, 1u) == (unsigned)(NBLOCKS - 1)) {
            g_bar_cnt = 0;
            __threadfence();                   // cnt reset visible before release
            g_bar_gen = gen + 1;               // release
        } else {
            while (g_bar_gen == gen) { __nanosleep(64); }
        }
        __threadfence();
    }
    __syncthreads();
}

// ---------------------------------------------------------------- kernel 0: zero accumulators
__global__ void eeg_zero_kernel() {
    int i = blockIdx.x * blockDim.x + threadIdx.x;
    if (i < BATCH * CH) { g_sum[i] = 0.f; g_sum2[i] = 0.f; }
}

// ---------------------------------------------------------------- kernel 1: persistent fused
// For each batch group: pipelined stats (each block: batch b0+by, chunks bx+k*GX),
// grid barrier, then grid-stride normalize of the group (x re-read hits L2).
__global__ __launch_bounds__(256) void eeg_fused_kernel(const float* __restrict__ x,
                                                        float4* __restrict__ o4) {
    extern __shared__ float s[];
    float* part = s + NBUF * TILE_FLOATS;      // 8 * TT
    float* mrow = part + 8 * TT;               // TT

    const int tid  = threadIdx.x;
    const int bidx = blockIdx.y * GX + blockIdx.x;

    // stats mappings
    const int irow  = tid >> 3;                // 0..31
    const int islot = tid & 7;                 // float4 slot (t = 4*islot)
    const int cs_t  = tid & 31;
    const int cs_g  = tid >> 5;
    const int p2_c  = tid & (CH - 1);
    const int p2_h  = tid >> 7;                // 0..1 -> t base h*16

    const unsigned sbase = (unsigned)__cvta_generic_to_shared(s);
    const float4* __restrict__ x4 = reinterpret_cast<const float4*>(x);

    for (int grp = 0; grp < GROUPS; ++grp) {
        const int b0 = grp * GBATCH;
        const int b  = b0 + blockIdx.y;
        const float* __restrict__ xb = x + (size_t)b * CH * T_LEN;

        // ================= stats phase =================
        float acc_sy = 0.f, acc_sy2 = 0.f;

        auto issue_chunk = [&](int chunk, int buf) {
            if (chunk < NCHUNK) {
                const int t0   = chunk * TT;
                const int vlen = min(TT, T_LEN - t0);
                const unsigned sb = sbase + (unsigned)(buf * TILE_FLOATS) * 4u;
                float* fb = s + buf * TILE_FLOATS;
                #pragma unroll
                for (int p = 0; p < 4; ++p) {
                    const int c = p * 32 + irow;
                    const int toff = 4 * islot;
                    if (toff < vlen) {
                        cp_async16(sb + (unsigned)(c * PITCH + toff) * 4u,
                                   xb + (size_t)c * T_LEN + t0 + toff);
                    } else {
                        *reinterpret_cast<float4*>(&fb[c * PITCH + toff]) =
                            make_float4(0.f, 0.f, 0.f, 0.f);
                    }
                }
            }
            cp_commit();   // empty group when chunk invalid keeps wait-counts aligned
        };

        auto compute_chunk = [&](int chunk, const float* tile) {
            const int t0   = chunk * TT;
            const int vlen = min(TT, T_LEN - t0);

            float csum = 0.f;
            const float* col = tile + (cs_g * 16) * PITCH + cs_t;
            #pragma unroll
            for (int c = 0; c < 16; ++c) csum += col[c * PITCH];
            part[cs_g * TT + cs_t] = csum;
            __syncthreads();

            if (tid < TT) {
                float m = 0.f;
                #pragma unroll
                for (int g = 0; g < 8; ++g) m += part[g * TT + tid];
                m *= (1.0f / 128.0f);
                mrow[tid] = m;
                if (tid < vlen) g_m[(size_t)b * T_LEN + t0 + tid] = m;
            }
            __syncthreads();

            const float* trow = tile + p2_c * PITCH + p2_h * 16;
            const float* mr   = mrow + p2_h * 16;
            #pragma unroll
            for (int tt = 0; tt < 16; tt += 4) {
                float4 v  = *reinterpret_cast<const float4*>(&trow[tt]);
                float4 m4 = *reinterpret_cast<const float4*>(&mr[tt]);
                float a0 = v.x - m4.x, a1 = v.y - m4.y, a2 = v.z - m4.z, a3 = v.w - m4.w;
                acc_sy  += (a0 + a1) + (a2 + a3);
                acc_sy2 += a0 * a0 + a1 * a1 + a2 * a2 + a3 * a3;
            }
        };

        const int first = blockIdx.x;
        int issue_k = first;
        #pragma unroll
        for (int d = 0; d < NBUF - 1; ++d) {   // prologue: 2 chunks in flight
            issue_chunk(issue_k, d);
            issue_k += GX;
        }
        int bufidx = 0;
        for (int k = first; k < NCHUNK; k += GX) {
            int ibuf = bufidx + (NBUF - 1); if (ibuf >= NBUF) ibuf -= NBUF;
            issue_chunk(issue_k, ibuf);
            issue_k += GX;
            cp_wait<NBUF - 1>();               // chunk k's group complete
            __syncthreads();
            compute_chunk(k, s + bufidx * TILE_FLOATS);
            __syncthreads();
            if (++bufidx == NBUF) bufidx = 0;
        }

        atomicAdd(&g_sum [b * CH + p2_c], acc_sy);
        atomicAdd(&g_sum2[b * CH + p2_c], acc_sy2);

        // ================= barrier: group stats complete =================
        grid_barrier();

        // ================= norm phase (grid-stride over group's tiles) =================
        // Work item w -> (bc_local = w/NTILE, tile = w%NTILE); 512 float4 per tile.
        const int nwork = GBATCH * CH * NTILE;          // 5120
        for (int w = bidx; w < nwork; w += NBLOCKS) {
            const int bc_local = w / NTILE;
            const int tile     = w - bc_local * NTILE;
            const int bc       = b0 * CH + bc_local;
            const int bb       = bc >> 7;

            const float inv_t = 1.0f / (float)T_LEN;
            float mean = g_sum[bc] * inv_t;
            float var  = g_sum2[bc] * inv_t - mean * mean;
            float sd   = sqrtf(fmaxf(var, 0.f));
            float istd = (sd == 0.f) ? 1.f : (1.f / sd);

            const float4* __restrict__ xp = x4 + (size_t)bc * T4;
            float4*                   op = o4 + (size_t)bc * T4;
            const float4* __restrict__ mp =
                reinterpret_cast<const float4*>(g_m + (size_t)bb * T_LEN);

            const int ta = tile * 512 + tid;
            const int tb = ta + 256;
            const bool va = ta < T4;
            const bool vb = tb < T4;

            float4 v0, v1, m0, m1;
            if (va) { v0 = xp[ta]; m0 = mp[ta]; }
            if (vb) { v1 = xp[tb]; m1 = mp[tb]; }

            if (va) {
                float4 r;
                r.x = (v0.x - m0.x - mean) * istd;
                r.y = (v0.y - m0.y - mean) * istd;
                r.z = (v0.z - m0.z - mean) * istd;
                r.w = (v0.w - m0.w - mean) * istd;
                op[ta] = r;
            }
            if (vb) {
                float4 r;
                r.x = (v1.x - m1.x - mean) * istd;
                r.y = (v1.y - m1.y - mean) * istd;
                r.z = (v1.z - m1.z - mean) * istd;
                r.w = (v1.w - m1.w - mean) * istd;
                op[tb] = r;
            }
        }
        // No barrier here: group g+1's stats writes are disjoint from group g's reads;
        // stragglers' norm writes overlap the next group's DRAM reads.
    }
}

// ---------------------------------------------------------------- launch
extern "C" void kernel_launch(void* const* d_in, const int* in_sizes, int n_in,
                              void* d_out, int out_size) {
    (void)in_sizes; (void)n_in; (void)out_size;
    const float* x = (const float*)d_in[0];
    float* out = (float*)d_out;

    static const size_t smem_bytes =
        (NBUF * TILE_FLOATS + 9 * TT) * sizeof(float);   // ~56.5 KB -> 4 blocks/SM
    cudaFuncSetAttribute(eeg_fused_kernel,
                         cudaFuncAttributeMaxDynamicSharedMemorySize,
                         (int)smem_bytes);

    eeg_zero_kernel<<<(BATCH * CH + 255) / 256, 256>>>();

    dim3 grid(GX, GBATCH);                     // (56, 8) = 448 blocks, all resident
    eeg_fused_kernel<<<grid, 256, smem_bytes>>>(x, (float4*)out);
}

// round 15
// speedup vs baseline: 1.1726x; 1.1726x over previous
#include <cuda_runtime.h>
#include <cstdint>
#include <math.h>

// Problem constants: x is (64, 128, 10000) fp32.
#define BATCH 64
#define CH    128
#define T_LEN 10000
#define TT    32            // time-chunk per pipeline stage
#define PITCH 36            // floats; 144B rows: 16B-aligned, ≡4 mod 32 banks
#define NCHUNK 313          // ceil(10000/32); last chunk vlen=16
#define GSTRIDE 9           // chunk stride -> grid (9,64) = 576 blocks ≈ 3.9/SM
#define NBUF  3             // pipeline depth (2 chunks in flight); 4 blocks/SM
#define T4    (T_LEN / 4)   // 2500
#define TILE_FLOATS (CH * PITCH)
#define NSLOT (GSTRIDE * 2) // partial-sum slots per (b,c)

// Scratch (no allocations allowed).
__device__ float g_m[BATCH * T_LEN];              // mean over channels at each (b,t)
__device__ float g_part_sy [NSLOT][BATCH * CH];   // per-(block,half) partial sums
__device__ float g_part_sy2[NSLOT][BATCH * CH];
__device__ float g_mean[BATCH * CH];
__device__ float g_istd[BATCH * CH];

__device__ __forceinline__ void cp_async16(unsigned sdst, const void* gsrc) {
    asm volatile("cp.async.cg.shared.global [%0], [%1], 16;\n"
                 :: "r"(sdst), "l"(gsrc));
}
__device__ __forceinline__ void cp_commit() {
    asm volatile("cp.async.commit_group;\n");
}
template <int N>
__device__ __forceinline__ void cp_wait() {
    asm volatile("cp.async.wait_group %0;\n" :: "n"(N));
}

// ---------------------------------------------------------------- kernel 1: pipelined stats
// 256 threads/block, 2 chunks in flight, 4 blocks/SM. Per-thread channel-stat
// accumulators live in registers across chunks; plain store to a private partial slot.
__global__ __launch_bounds__(256) void eeg_stats_kernel(const float* __restrict__ x) {
    extern __shared__ float s[];
    float* part = s + NBUF * TILE_FLOATS;      // 8 * TT  (per-group colsum partials)
    float* mrow = part + 8 * TT;               // TT      (channel mean per t)

    const int b   = blockIdx.y;
    const int tid = threadIdx.x;

    const int irow  = tid >> 3;                // 0..31
    const int islot = tid & 7;                 // float4 slot (t = 4*islot)
    const int cs_t = tid & 31;
    const int cs_g = tid >> 5;
    const int p2_c = tid & (CH - 1);
    const int p2_h = tid >> 7;                 // 0..1 -> t base h*16

    const float* __restrict__ xb = x + (size_t)b * CH * T_LEN;
    const unsigned sbase = (unsigned)__cvta_generic_to_shared(s);

    float acc_sy = 0.f, acc_sy2 = 0.f;

    auto issue_chunk = [&](int chunk, int buf) {
        if (chunk < NCHUNK) {
            const int t0   = chunk * TT;
            const int vlen = min(TT, T_LEN - t0);
            const unsigned sb = sbase + (unsigned)(buf * TILE_FLOATS) * 4u;
            float* fb = s + buf * TILE_FLOATS;
            #pragma unroll
            for (int p = 0; p < 4; ++p) {
                const int c = p * 32 + irow;
                const int toff = 4 * islot;
                if (toff < vlen) {
                    cp_async16(sb + (unsigned)(c * PITCH + toff) * 4u,
                               xb + (size_t)c * T_LEN + t0 + toff);
                } else {
                    *reinterpret_cast<float4*>(&fb[c * PITCH + toff]) =
                        make_float4(0.f, 0.f, 0.f, 0.f);
                }
            }
        }
        cp_commit();   // empty group when chunk invalid keeps wait-counts aligned
    };

    auto compute_chunk = [&](int chunk, const float* tile) {
        const int t0   = chunk * TT;
        const int vlen = min(TT, T_LEN - t0);

        // colsum: group g sums 16 channels at time cs_t (conflict-free scalar LDS)
        float csum = 0.f;
        const float* col = tile + (cs_g * 16) * PITCH + cs_t;
        #pragma unroll
        for (int c = 0; c < 16; ++c) csum += col[c * PITCH];
        part[cs_g * TT + cs_t] = csum;
        __syncthreads();

        // combine 8 partials -> mrow, g_m (first 32 threads)
        if (tid < TT) {
            float m = 0.f;
            #pragma unroll
            for (int g = 0; g < 8; ++g) m += part[g * TT + tid];
            m *= (1.0f / 128.0f);
            mrow[tid] = m;
            if (tid < vlen) g_m[(size_t)b * T_LEN + t0 + tid] = m;
        }
        __syncthreads();

        // per-channel accumulation: (c, h) covers t in [h*16, h*16+16) via LDS.128
        const float* trow = tile + p2_c * PITCH + p2_h * 16;
        const float* mr   = mrow + p2_h * 16;
        #pragma unroll
        for (int tt = 0; tt < 16; tt += 4) {
            float4 v  = *reinterpret_cast<const float4*>(&trow[tt]);
            float4 m4 = *reinterpret_cast<const float4*>(&mr[tt]);    // broadcast
            float a0 = v.x - m4.x, a1 = v.y - m4.y, a2 = v.z - m4.z, a3 = v.w - m4.w;
            acc_sy  += (a0 + a1) + (a2 + a3);          // zero-filled tail contributes 0
            acc_sy2 += a0 * a0 + a1 * a1 + a2 * a2 + a3 * a3;
        }
    };

    // ---- pipeline: 2 chunks in flight ----
    const int first = blockIdx.x;
    int issue_k = first;
    #pragma unroll
    for (int d = 0; d < NBUF - 1; ++d) {
        issue_chunk(issue_k, d);
        issue_k += GSTRIDE;
    }

    int bufidx = 0;
    for (int k = first; k < NCHUNK; k += GSTRIDE) {
        int ibuf = bufidx + (NBUF - 1); if (ibuf >= NBUF) ibuf -= NBUF;
        issue_chunk(issue_k, ibuf);
        issue_k += GSTRIDE;
        cp_wait<NBUF - 1>();            // chunk k's group complete
        __syncthreads();                // its STS (and zero-fills) visible to all
        compute_chunk(k, s + bufidx * TILE_FLOATS);
        __syncthreads();                // buffer reusable for next issue
        if (++bufidx == NBUF) bufidx = 0;
    }

    // private partial slot -> no atomics, no pre-zeroing
    const int slot = blockIdx.x * 2 + p2_h;
    g_part_sy [slot][b * CH + p2_c] = acc_sy;
    g_part_sy2[slot][b * CH + p2_c] = acc_sy2;
}

// ---------------------------------------------------------------- kernel 2: finalize
// Sum 18 partial slots -> mean / inv_std.
__global__ void eeg_finalize_kernel() {
    int i = blockIdx.x * blockDim.x + threadIdx.x;
    if (i < BATCH * CH) {
        float sy = 0.f, sy2 = 0.f;
        #pragma unroll
        for (int sidx = 0; sidx < NSLOT; ++sidx) {
            sy  += g_part_sy [sidx][i];
            sy2 += g_part_sy2[sidx][i];
        }
        const float inv_t = 1.0f / (float)T_LEN;
        float mean = sy * inv_t;
        float var  = sy2 * inv_t - mean * mean;
        float sd   = sqrtf(fmaxf(var, 0.f));
        g_mean[i] = mean;
        g_istd[i] = (sd == 0.f) ? 1.f : (1.f / sd);
    }
}

// ---------------------------------------------------------------- kernel 3: normalize
// grid = (5, 8192): blockIdx.y = (b,c) pair. 2 float4 per thread, loads front-batched.
__global__ __launch_bounds__(256) void eeg_norm_kernel(const float4* __restrict__ x4,
                                                       float4* __restrict__ o4) {
    const int bc = blockIdx.y;
    const int b  = bc >> 7;
    const int ta = blockIdx.x * 512 + threadIdx.x;
    const int tb = ta + 256;

    const float mean = g_mean[bc];
    const float istd = g_istd[bc];

    const float4* __restrict__ xp = x4 + (size_t)bc * T4;
    float4*                   op = o4 + (size_t)bc * T4;
    const float4* __restrict__ mp =
        reinterpret_cast<const float4*>(g_m + (size_t)b * T_LEN);

    const bool va = ta < T4;
    const bool vb = tb < T4;

    float4 v0, v1, m0, m1;
    if (va) { v0 = xp[ta]; m0 = mp[ta]; }
    if (vb) { v1 = xp[tb]; m1 = mp[tb]; }

    if (va) {
        float4 r;
        r.x = (v0.x - m0.x - mean) * istd;
        r.y = (v0.y - m0.y - mean) * istd;
        r.z = (v0.z - m0.z - mean) * istd;
        r.w = (v0.w - m0.w - mean) * istd;
        op[ta] = r;
    }
    if (vb) {
        float4 r;
        r.x = (v1.x - m1.x - mean) * istd;
        r.y = (v1.y - m1.y - mean) * istd;
        r.z = (v1.z - m1.z - mean) * istd;
        r.w = (v1.w - m1.w - mean) * istd;
        op[tb] = r;
    }
}

// ---------------------------------------------------------------- launch
extern "C" void kernel_launch(void* const* d_in, const int* in_sizes, int n_in,
                              void* d_out, int out_size) {
    (void)in_sizes; (void)n_in; (void)out_size;
    const float* x = (const float*)d_in[0];
    float* out = (float*)d_out;

    static const size_t smem_bytes =
        (NBUF * TILE_FLOATS + 9 * TT) * sizeof(float);   // ~56.4 KB -> 4 blocks/SM
    cudaFuncSetAttribute(eeg_stats_kernel,
                         cudaFuncAttributeMaxDynamicSharedMemorySize,
                         (int)smem_bytes);

    // 1) pipelined stats (no atomics: private partial slots)
    dim3 sgrid(GSTRIDE, BATCH);                  // (9, 64) = 576 blocks
    eeg_stats_kernel<<<sgrid, 256, smem_bytes>>>(x);

    // 2) finalize mean / inv_std from partials
    eeg_finalize_kernel<<<(BATCH * CH + 255) / 256, 256>>>();

    // 3) normalize
    dim3 ngrid((T4 + 511) / 512, BATCH * CH);    // (5, 8192)
    eeg_norm_kernel<<<ngrid, 256>>>((const float4*)x, (float4*)out);
}